// round 15
// baseline (speedup 1.0000x reference)
#include <cuda_runtime.h>
#include <math.h>
#include <stdint.h>

#define B_    8
#define CCH   256
#define NPIX  1024
#define HID   1024
#define NTOK  (B_ * NPIX)   // 8192

__device__ float g_scratch[132ull * 1024 * 1024];

extern __shared__ char dyn_smem[];

__device__ __forceinline__ float to_tf32(float x) {
    float r;
    asm("cvt.rna.tf32.f32 %0, %1;" : "=f"(r) : "f"(x));
    return r;
}
__device__ __forceinline__ uint32_t smem_addr(const void* p) {
    return (uint32_t)__cvta_generic_to_shared(p);
}
__device__ __forceinline__ void cp16(uint32_t dst, const void* src) {
    asm volatile("cp.async.ca.shared.global [%0], [%1], 16;" :: "r"(dst), "l"(src));
}
// k-permutation within each 8-block: newpos(k) = (k&3)*2 + ((k>>2)&1)
__device__ __forceinline__ int permk(int k) {
    return (k & ~7) | (((k & 3) << 1) | ((k >> 2) & 1));
}

#define MMA_TF32(acc, a0, a1, a2, a3, b0, b1) \
    asm volatile( \
        "mma.sync.aligned.m16n8k8.row.col.f32.tf32.tf32.f32 " \
        "{%0,%1,%2,%3}, {%4,%5,%6,%7}, {%8,%9}, {%0,%1,%2,%3};" \
        : "+f"((acc)[0]), "+f"((acc)[1]), "+f"((acc)[2]), "+f"((acc)[3]) \
        : "r"(a0), "r"(a1), "r"(a2), "r"(a3), "r"(b0), "r"(b1))

// ---------------------------------------------------------------------------
// fused weight prep: tf32-round + k-permute + optional scale, one launch.
// ---------------------------------------------------------------------------
struct PrepArgs {
    const float* src[14];
    float*       dst[14];
    int          len[14];
    float        scl[14];
};
__global__ __launch_bounds__(256)
void prep_all(PrepArgs a)
{
    int i = blockIdx.x * 256 + threadIdx.x;
#pragma unroll
    for (int s = 0; s < 14; s++) {
        if (i < a.len[s]) {
            a.dst[s][permk(i)] = to_tf32(__ldg(a.src[s] + i) * a.scl[s]);
            return;
        }
        i -= a.len[s];
    }
}

// ---------------------------------------------------------------------------
// Dual-descriptor tf32 mma.sync GEMM. blockIdx.z < 8 -> d0, else d1 (uniform
// per block). PRE-PERMUTED tf32 inputs; fp32 Y (+R); rnd -> tf32 outputs;
// transY -> channel-major store. Block 128x128x32, cp.async double buffer.
// ---------------------------------------------------------------------------
struct GD {
    const float* A; const float* W; const float* R; float* Y;
    int ldA, ldR, ldY, K, transY, rnd;
};
__global__ __launch_bounds__(256, 2)
void gemm_tc(GD d0, GD d1)
{
    const GD d = (blockIdx.z < 8) ? d0 : d1;
    const int bz = blockIdx.z & 7;

    float* As = (float*)dyn_smem;        // [2][128*40]
    float* Bs = As + 2 * 5120;           // [2][128*40]

    const int t = threadIdx.x;
    const int wid = t >> 5, lane = t & 31;
    const int g = lane >> 2, tig = lane & 3;
    const int warp_m = (wid & 1) * 64;
    const int warp_n = (wid >> 1) * 32;
    const int r0l = t >> 3, q0l = t & 7;

    const float* Ab = d.A + (size_t)bz * NPIX * d.ldA + (size_t)blockIdx.x * 128 * d.ldA;
    const float* Bb = d.W + (size_t)blockIdx.y * 128 * (size_t)d.K;

    const uint32_t sA = smem_addr(As), sB = smem_addr(Bs);

    float acc[4][4][4];
#pragma unroll
    for (int im = 0; im < 4; im++)
#pragma unroll
        for (int in = 0; in < 4; in++)
#pragma unroll
            for (int c = 0; c < 4; c++) acc[im][in][c] = 0.f;

    const int nk = d.K >> 5;

#pragma unroll
    for (int i = 0; i < 4; i++) {
        const int r = r0l + i * 32;
        cp16(sA + (uint32_t)(r * 40 + q0l * 4) * 4, Ab + (size_t)r * d.ldA + q0l * 4);
        cp16(sB + (uint32_t)(r * 40 + q0l * 4) * 4, Bb + (size_t)r * d.K   + q0l * 4);
    }
    asm volatile("cp.async.commit_group;");

    for (int c = 0; c < nk; c++) {
        asm volatile("cp.async.wait_group 0;");
        __syncthreads();
        if (c + 1 < nk) {
            const int kk = (c + 1) << 5;
            const uint32_t boff = (uint32_t)((c + 1) & 1) * 5120;
#pragma unroll
            for (int i = 0; i < 4; i++) {
                const int r = r0l + i * 32;
                cp16(sA + (boff + r * 40 + q0l * 4) * 4, Ab + (size_t)r * d.ldA + kk + q0l * 4);
                cp16(sB + (boff + r * 40 + q0l * 4) * 4, Bb + (size_t)r * d.K   + kk + q0l * 4);
            }
            asm volatile("cp.async.commit_group;");
        }
        const float* Ac = As + (c & 1) * 5120;
        const float* Bc = Bs + (c & 1) * 5120;
#pragma unroll
        for (int ks = 0; ks < 4; ks++) {
            const int k0 = ks * 8;
            float2 au[4], al[4];
#pragma unroll
            for (int im = 0; im < 4; im++) {
                au[im] = *(const float2*)&Ac[(warp_m + im * 16 + g) * 40 + k0 + 2 * tig];
                al[im] = *(const float2*)&Ac[(warp_m + im * 16 + g + 8) * 40 + k0 + 2 * tig];
            }
#pragma unroll
            for (int in = 0; in < 4; in++) {
                const float2 bv = *(const float2*)&Bc[(warp_n + in * 8 + g) * 40 + k0 + 2 * tig];
#pragma unroll
                for (int im = 0; im < 4; im++) {
                    MMA_TF32(acc[im][in],
                             __float_as_uint(au[im].x), __float_as_uint(al[im].x),
                             __float_as_uint(au[im].y), __float_as_uint(al[im].y),
                             __float_as_uint(bv.x), __float_as_uint(bv.y));
                }
            }
        }
    }

    if (!d.transY) {
        float* Yb = d.Y + (size_t)bz * NPIX * d.ldY;
        const float* Rb = d.R ? d.R + (size_t)bz * NPIX * d.ldR : (const float*)0;
#pragma unroll
        for (int im = 0; im < 4; im++) {
#pragma unroll
            for (int half = 0; half < 2; half++) {
                const int tok = blockIdx.x * 128 + warp_m + im * 16 + g + half * 8;
#pragma unroll
                for (int in = 0; in < 4; in++) {
                    const int col = blockIdx.y * 128 + warp_n + in * 8 + tig * 2;
                    float2 v;
                    v.x = acc[im][in][half * 2 + 0];
                    v.y = acc[im][in][half * 2 + 1];
                    if (Rb) {
                        float2 rr = *(const float2*)(Rb + (size_t)tok * d.ldR + col);
                        v.x += rr.x; v.y += rr.y;
                    }
                    if (d.rnd) { v.x = to_tf32(v.x); v.y = to_tf32(v.y); }
                    *(float2*)(Yb + (size_t)tok * d.ldY + col) = v;
                }
            }
        }
    } else {
        float* Yb = d.Y + (size_t)bz * d.ldY * NPIX;
        const float* Rb = d.R ? d.R + (size_t)bz * NPIX * d.ldR : (const float*)0;
#pragma unroll
        for (int im = 0; im < 4; im++) {
#pragma unroll
            for (int half = 0; half < 2; half++) {
                const int tok = blockIdx.x * 128 + warp_m + im * 16 + g + half * 8;
#pragma unroll
                for (int in = 0; in < 4; in++) {
                    const int col = blockIdx.y * 128 + warp_n + in * 8 + tig * 2;
                    float v0 = acc[im][in][half * 2 + 0];
                    float v1 = acc[im][in][half * 2 + 1];
                    if (Rb) {
                        float2 rr = *(const float2*)(Rb + (size_t)tok * d.ldR + col);
                        v0 += rr.x; v1 += rr.y;
                    }
                    if (d.rnd) { v0 = to_tf32(v0); v1 = to_tf32(v1); }
                    Yb[(size_t)(col + 0) * NPIX + tok] = v0;
                    Yb[(size_t)(col + 1) * NPIX + tok] = v1;
                }
            }
        }
    }
}

// ---------------------------------------------------------------------------
// im2col: NCHW -> [B][1024 tok][C*KS*KS], tf32-rounded, k-permuted.
// ---------------------------------------------------------------------------
template <int KS>
__global__ __launch_bounds__(256)
void im2col_kernel(const float* __restrict__ in, float* __restrict__ out)
{
    constexpr int PAD  = KS / 2;
    constexpr int TAPS = KS * KS;
    constexpr int KTOT = CCH * TAPS;
    __shared__ float smv[64 * KS * 36];
    const int c0 = blockIdx.x * 64;
    const int h  = blockIdx.y;
    const int b  = blockIdx.z;
    const int t  = threadIdx.x;

    for (int e = t; e < 64 * KS * 36; e += 256) {
        const int cc = e % 36;
        const int r  = (e / 36) % KS;
        const int c  = e / (36 * KS);
        const int hh = h + r - PAD;
        const int ww = cc - PAD;
        float v = 0.f;
        if (hh >= 0 && hh < 32 && ww >= 0 && ww < 32)
            v = in[((size_t)b * CCH + c0 + c) * NPIX + hh * 32 + ww];
        smv[(c * KS + r) * 36 + cc] = v;
    }
    __syncthreads();
    for (int e = t; e < 32 * 64 * TAPS; e += 256) {
        const int w   = e / (64 * TAPS);
        const int rem = e % (64 * TAPS);
        const int c   = rem / TAPS;
        const int tap = rem % TAPS;
        const int ky  = tap / KS, kx = tap % KS;
        const int k   = (c0 + c) * TAPS + tap;
        out[((size_t)b * NPIX + h * 32 + w) * KTOT + permk(k)] =
            to_tf32(smv[(c * KS + ky) * 36 + (w + kx)]);
    }
}

// ---------------------------------------------------------------------------
// Dual LayerNorm over channels, token-major [8192][256]. Warp per token.
// blockIdx.x < 1024 -> set0 else set1. Output tf32 + k-permuted.
// ---------------------------------------------------------------------------
struct LD { const float* x; const float* w; const float* b; float* y; };
__global__ __launch_bounds__(256)
void ln_kernel(LD d0, LD d1)
{
    const LD d = (blockIdx.x < 1024) ? d0 : d1;
    const int bx = blockIdx.x & 1023;
    const int warp = threadIdx.x >> 5, lane = threadIdx.x & 31;
    const size_t tok = (size_t)bx * 8 + warp;
    const float* xr = d.x + tok * CCH;
    float4 v0 = *(const float4*)(xr + lane * 4);
    float4 v1 = *(const float4*)(xr + 128 + lane * 4);
    float s  = v0.x + v0.y + v0.z + v0.w + v1.x + v1.y + v1.z + v1.w;
    float s2 = v0.x*v0.x + v0.y*v0.y + v0.z*v0.z + v0.w*v0.w
             + v1.x*v1.x + v1.y*v1.y + v1.z*v1.z + v1.w*v1.w;
#pragma unroll
    for (int o = 16; o > 0; o >>= 1) {
        s  += __shfl_xor_sync(0xffffffffu, s,  o);
        s2 += __shfl_xor_sync(0xffffffffu, s2, o);
    }
    const float mu = s * (1.f / 256.f);
    const float is = rsqrtf(s2 * (1.f / 256.f) - mu * mu + 1e-5f);
    float4 w0 = *(const float4*)(d.w + lane * 4);
    float4 w1 = *(const float4*)(d.w + 128 + lane * 4);
    float4 b0 = *(const float4*)(d.b + lane * 4);
    float4 b1 = *(const float4*)(d.b + 128 + lane * 4);
    float* yr = d.y + tok * CCH;
    float r0[4], r1[4];
    r0[0] = (v0.x - mu) * is * w0.x + b0.x; r0[1] = (v0.y - mu) * is * w0.y + b0.y;
    r0[2] = (v0.z - mu) * is * w0.z + b0.z; r0[3] = (v0.w - mu) * is * w0.w + b0.w;
    r1[0] = (v1.x - mu) * is * w1.x + b1.x; r1[1] = (v1.y - mu) * is * w1.y + b1.y;
    r1[2] = (v1.z - mu) * is * w1.z + b1.z; r1[3] = (v1.w - mu) * is * w1.w + b1.w;
#pragma unroll
    for (int j = 0; j < 4; j++) {
        yr[permk(lane * 4 + j)]       = to_tf32(r0[j]);
        yr[permk(128 + lane * 4 + j)] = to_tf32(r1[j]);
    }
}

// ---------------------------------------------------------------------------
// Dual flash attention, tf32 mma. blockIdx.z < 8 -> d0 else d1.
// qk [B][1024][512] tf32 (Q pre-scaled 1/8), vT [B][256][1024] tf32.
// cp.async staging, 2 CTAs/SM. out [B][1024][256] tf32 k-permuted.
// ---------------------------------------------------------------------------
struct AD { const float* qk; const float* vT; float* out; };
__global__ __launch_bounds__(256, 2)
void attn_kernel(AD d0, AD d1)
{
    const AD d = (blockIdx.z < 8) ? d0 : d1;
    const int b = blockIdx.z & 7;

    float* sm = (float*)dyn_smem;
    float* Qs = sm;                      // [128][68]
    float* Ks = Qs + 128 * 68;           // [64][68]
    float* Vt = Ks + 64 * 68;            // [64][68]
    float* Ps = Vt + 64 * 68;            // [128][68]

    const int h = blockIdx.y;
    const int q0 = blockIdx.x * 128;
    const int hq = h * 64;
    const float* qkb = d.qk + (size_t)b * NPIX * 512;
    const float* vtb = d.vT + ((size_t)b * 256 + hq) * NPIX;

    const int t = threadIdx.x;
    const int wid = t >> 5, lane = t & 31;
    const int g = lane >> 2, tig = lane & 3;
    const int w16 = wid * 16;

    const uint32_t sQ = smem_addr(Qs), sK = smem_addr(Ks), sV = smem_addr(Vt);

#pragma unroll
    for (int i = 0; i < 8; i++) {
        const int e = t + i * 256;
        const int r = e >> 4, c = e & 15;
        cp16(sQ + (uint32_t)(r * 68 + c * 4) * 4,
             qkb + (size_t)(q0 + r) * 512 + hq + c * 4);
    }
#pragma unroll
    for (int i = 0; i < 4; i++) {
        const int e = t + i * 256;
        const int rk = e >> 4, ck = e & 15;
        cp16(sK + (uint32_t)(rk * 68 + ck * 4) * 4, qkb + (size_t)rk * 512 + 256 + hq + ck * 4);
        cp16(sV + (uint32_t)(rk * 68 + ck * 4) * 4, vtb + (size_t)rk * NPIX + ck * 4);
    }
    asm volatile("cp.async.commit_group;");

    float oc[8][4];
#pragma unroll
    for (int n = 0; n < 8; n++)
#pragma unroll
        for (int c = 0; c < 4; c++) oc[n][c] = 0.f;
    float m0r = -1e30f, m1r = -1e30f, l0r = 0.f, l1r = 0.f;

    const int P0 = ((tig & 1) << 2) | (tig >> 1);

    for (int tile = 0; tile < 16; tile++) {
        asm volatile("cp.async.wait_group 0;");
        __syncthreads();

        float s[8][4];
#pragma unroll
        for (int n = 0; n < 8; n++)
#pragma unroll
            for (int c = 0; c < 4; c++) s[n][c] = 0.f;
#pragma unroll
        for (int ks = 0; ks < 8; ks++) {
            const int k0 = ks * 8;
            const uint32_t a0 = __float_as_uint(Qs[(w16 + g) * 68 + k0 + tig]);
            const uint32_t a1 = __float_as_uint(Qs[(w16 + g + 8) * 68 + k0 + tig]);
            const uint32_t a2 = __float_as_uint(Qs[(w16 + g) * 68 + k0 + tig + 4]);
            const uint32_t a3 = __float_as_uint(Qs[(w16 + g + 8) * 68 + k0 + tig + 4]);
#pragma unroll
            for (int n = 0; n < 8; n++) {
                const uint32_t b0 = __float_as_uint(Ks[(n * 8 + g) * 68 + k0 + tig]);
                const uint32_t b1 = __float_as_uint(Ks[(n * 8 + g) * 68 + k0 + tig + 4]);
                MMA_TF32(s[n], a0, a1, a2, a3, b0, b1);
            }
        }

        float t0 = -1e30f, t1 = -1e30f;
#pragma unroll
        for (int n = 0; n < 8; n++) {
            t0 = fmaxf(t0, fmaxf(s[n][0], s[n][1]));
            t1 = fmaxf(t1, fmaxf(s[n][2], s[n][3]));
        }
        t0 = fmaxf(t0, __shfl_xor_sync(0xffffffffu, t0, 1));
        t0 = fmaxf(t0, __shfl_xor_sync(0xffffffffu, t0, 2));
        t1 = fmaxf(t1, __shfl_xor_sync(0xffffffffu, t1, 1));
        t1 = fmaxf(t1, __shfl_xor_sync(0xffffffffu, t1, 2));
        const float nm0 = fmaxf(m0r, t0), nm1 = fmaxf(m1r, t1);
        const float cr0 = __expf(m0r - nm0), cr1 = __expf(m1r - nm1);
        m0r = nm0; m1r = nm1;
        float ls0 = 0.f, ls1 = 0.f;
#pragma unroll
        for (int n = 0; n < 8; n++) {
            const float p0 = __expf(s[n][0] - nm0);
            const float p1 = __expf(s[n][1] - nm0);
            const float p2 = __expf(s[n][2] - nm1);
            const float p3 = __expf(s[n][3] - nm1);
            ls0 += p0 + p1; ls1 += p2 + p3;
            float2 pa; pa.x = to_tf32(p0); pa.y = to_tf32(p1);
            float2 pb; pb.x = to_tf32(p2); pb.y = to_tf32(p3);
            *(float2*)&Ps[(w16 + g) * 68 + n * 8 + tig * 2] = pa;
            *(float2*)&Ps[(w16 + g + 8) * 68 + n * 8 + tig * 2] = pb;
        }
        ls0 += __shfl_xor_sync(0xffffffffu, ls0, 1);
        ls0 += __shfl_xor_sync(0xffffffffu, ls0, 2);
        ls1 += __shfl_xor_sync(0xffffffffu, ls1, 1);
        ls1 += __shfl_xor_sync(0xffffffffu, ls1, 2);
        l0r = l0r * cr0 + ls0;
        l1r = l1r * cr1 + ls1;
#pragma unroll
        for (int n = 0; n < 8; n++) {
            oc[n][0] *= cr0; oc[n][1] *= cr0;
            oc[n][2] *= cr1; oc[n][3] *= cr1;
        }
        __syncwarp();

#pragma unroll
        for (int ks = 0; ks < 8; ks++) {
            const int k0 = ks * 8;
            const uint32_t a0 = __float_as_uint(Ps[(w16 + g) * 68 + k0 + tig]);
            const uint32_t a1 = __float_as_uint(Ps[(w16 + g + 8) * 68 + k0 + tig]);
            const uint32_t a2 = __float_as_uint(Ps[(w16 + g) * 68 + k0 + tig + 4]);
            const uint32_t a3 = __float_as_uint(Ps[(w16 + g + 8) * 68 + k0 + tig + 4]);
#pragma unroll
            for (int n = 0; n < 8; n++) {
                const uint32_t b0 = __float_as_uint(Vt[(n * 8 + g) * 68 + k0 + tig]);
                const uint32_t b1 = __float_as_uint(Vt[(n * 8 + g) * 68 + k0 + tig + 4]);
                MMA_TF32(oc[n], a0, a1, a2, a3, b0, b1);
            }
        }

        if (tile < 15) {
            __syncthreads();
            const size_t m0 = (size_t)(tile + 1) * 64;
#pragma unroll
            for (int i = 0; i < 4; i++) {
                const int e = t + i * 256;
                const int rk = e >> 4, ck = e & 15;
                cp16(sK + (uint32_t)(rk * 68 + ck * 4) * 4,
                     qkb + (m0 + rk) * 512 + 256 + hq + ck * 4);
                cp16(sV + (uint32_t)(rk * 68 + ck * 4) * 4,
                     vtb + (size_t)rk * NPIX + m0 + ck * 4);
            }
            asm volatile("cp.async.commit_group;");
        }
    }

    const float i0 = 1.f / l0r, i1 = 1.f / l1r;
    float* ob = d.out + (size_t)b * NPIX * CCH;
#pragma unroll
    for (int n = 0; n < 8; n++) {
        float* r0p = ob + (size_t)(q0 + w16 + g) * CCH + hq + n * 8;
        float* r1p = ob + (size_t)(q0 + w16 + g + 8) * CCH + hq + n * 8;
        r0p[P0]     = to_tf32(oc[n][0] * i0);
        r0p[P0 + 2] = to_tf32(oc[n][1] * i0);
        r1p[P0]     = to_tf32(oc[n][2] * i1);
        r1p[P0 + 2] = to_tf32(oc[n][3] * i1);
    }
}

// ---------------------------------------------------------------------------
// Depthwise 3x3 + exact GELU, token-major [8192][1024].
// ---------------------------------------------------------------------------
__global__ __launch_bounds__(256)
void dwgelu_kernel(const float* __restrict__ x, const float* __restrict__ wd,
                   float* __restrict__ y)
{
    __shared__ float tile[10][34][32];
    const int c0 = blockIdx.x * 32;
    const int r0 = blockIdx.y * 8;
    const int b  = blockIdx.z;
    const int t  = threadIdx.x;
    const int ch = t & 31;

    for (int e = t; e < 10 * 34 * 32; e += 256) {
        const int cc  = e & 31;
        const int col = (e >> 5) % 34;
        const int r   = e / (34 * 32);
        const int hh = r0 + r - 1, ww = col - 1;
        float v = 0.f;
        if (hh >= 0 && hh < 32 && ww >= 0 && ww < 32)
            v = x[((size_t)b * NPIX + hh * 32 + ww) * HID + c0 + cc];
        tile[r][col][cc] = v;
    }
    float w9[9];
#pragma unroll
    for (int i = 0; i < 9; i++) w9[i] = wd[(size_t)(c0 + ch) * 9 + i];
    const int pc = permk(c0 + ch);
    __syncthreads();

    for (int e = t; e < 8 * 32 * 32; e += 256) {
        const int w = (e >> 5) & 31;
        const int r = e >> 10;
        float a = 0.f;
#pragma unroll
        for (int ky = 0; ky < 3; ky++)
#pragma unroll
            for (int kx = 0; kx < 3; kx++)
                a += w9[ky * 3 + kx] * tile[r + ky][w + kx][ch];
        y[((size_t)b * NPIX + (r0 + r) * 32 + w) * HID + pc] =
            to_tf32(0.5f * a * (1.f + erff(a * 0.70710678118654752f)));
    }
}

// ---------------------------------------------------------------------------
extern "C" void kernel_launch(void* const* d_in, const int* in_sizes, int n_in,
                              void* d_out, int out_size)
{
    const float* aop      = (const float*)d_in[0];
    const float* dop      = (const float*)d_in[1];
    const float* w_qconv  = (const float*)d_in[2];
    const float* w_kvconv = (const float*)d_in[3];
    const float* lnq1_w   = (const float*)d_in[4];
    const float* lnq1_b   = (const float*)d_in[5];
    const float* lnkv1_w  = (const float*)d_in[6];
    const float* lnkv1_b  = (const float*)d_in[7];
    const float* lnq2_w   = (const float*)d_in[8];
    const float* lnq2_b   = (const float*)d_in[9];
    const float* lnkv2_w  = (const float*)d_in[10];
    const float* lnkv2_b  = (const float*)d_in[11];
    const float* lnffn_w  = (const float*)d_in[12];
    const float* lnffn_b  = (const float*)d_in[13];
    const float* saq_qkv  = (const float*)d_in[14];
    const float* saq_proj = (const float*)d_in[15];
    const float* sakv_qkv = (const float*)d_in[16];
    const float* sakv_proj= (const float*)d_in[17];
    const float* ca_q     = (const float*)d_in[18];
    const float* ca_k     = (const float*)d_in[19];
    const float* ca_v     = (const float*)d_in[20];
    const float* ca_proj  = (const float*)d_in[21];
    const float* leff_in  = (const float*)d_in[22];
    const float* leff_dw  = (const float*)d_in[23];
    const float* leff_out = (const float*)d_in[24];
    float* out = (float*)d_out;

    float* S = nullptr;
    cudaGetSymbolAddress((void**)&S, g_scratch);
    const size_t C2 = (size_t)NTOK * CCH;       // 2M
    float* ic3   = S;                           // 18.9M
    float* ic5   = ic3  + (size_t)NTOK * 2304;
    float* qb    = ic5  + (size_t)NTOK * 6400;
    float* kvb   = qb   + C2;
    float* lnbq  = kvb  + C2;
    float* lnbkv = lnbq + C2;
    float* qn    = lnbkv+ C2;
    float* kvn   = qn   + C2;
    float* attq  = kvn  + C2;
    float* attkv = attq + C2;
    float* xbuf  = attkv+ C2;
    float* qkBq  = xbuf + C2;                   // 4M
    float* qkBkv = qkBq + (size_t)NTOK * 512;
    float* vTq   = qkBkv+ (size_t)NTOK * 512;
    float* vTkv  = vTq  + C2;
    float* h1    = vTkv + C2;
    float* h2    = h1   + (size_t)NTOK * HID;
    float* wp    = h2   + (size_t)NTOK * HID;

    float* p_wq3   = wp;
    float* p_wk5   = p_wq3   + 589824;
    float* p_saqkv = p_wk5   + 1638400;
    float* p_saprj = p_saqkv + 196608;
    float* p_skqkv = p_saprj + 65536;
    float* p_skprj = p_skqkv + 196608;
    float* p_caq   = p_skprj + 65536;
    float* p_cak   = p_caq   + 65536;
    float* p_cav   = p_cak   + 65536;
    float* p_caprj = p_cav   + 65536;
    float* p_lin   = p_caprj + 65536;
    float* p_lout  = p_lin   + 262144;

    const int GEMM_SM = 2 * 5120 * 2 * 4;    // 81920
    const int ATTN_SM = (128 * 68 + 64 * 68 + 64 * 68 + 128 * 68) * 4; // 104448
    cudaFuncSetAttribute(gemm_tc,     cudaFuncAttributeMaxDynamicSharedMemorySize, GEMM_SM);
    cudaFuncSetAttribute(attn_kernel, cudaFuncAttributeMaxDynamicSharedMemorySize, ATTN_SM);

    // fused weight prep. Q-projection rows pre-scaled by 0.125 (exact).
    PrepArgs pa;
    int s = 0;
    auto seg = [&](const float* src, float* dst, int len, float scl) {
        pa.src[s] = src; pa.dst[s] = dst; pa.len[s] = len; pa.scl[s] = scl; s++;
    };
    seg(w_qconv,          p_wq3,            589824,  1.f);
    seg(w_kvconv,         p_wk5,            1638400, 1.f);
    seg(saq_qkv,          p_saqkv,          65536,   0.125f);
    seg(saq_qkv + 65536,  p_saqkv + 65536,  131072,  1.f);
    seg(saq_proj,         p_saprj,          65536,   1.f);
    seg(sakv_qkv,         p_skqkv,          65536,   0.125f);
    seg(sakv_qkv + 65536, p_skqkv + 65536,  131072,  1.f);
    seg(sakv_proj,        p_skprj,          65536,   1.f);
    seg(ca_q,             p_caq,            65536,   0.125f);
    seg(ca_k,             p_cak,            65536,   1.f);
    seg(ca_v,             p_cav,            65536,   1.f);
    seg(ca_proj,          p_caprj,          65536,   1.f);
    seg(leff_in,          p_lin,            262144,  1.f);
    seg(leff_out,         p_lout,           262144,  1.f);
    int prep_total = 589824 + 1638400 + 2 * 196608 + 6 * 65536 + 2 * 262144;
    prep_all<<<(prep_total + 255) / 256, 256>>>(pa);

    auto mk = [](const float* A, int ldA, const float* W, const float* R, int ldR,
                 float* Y, int ldY, int K, int tY, int rnd) {
        GD g; g.A = A; g.W = W; g.R = R; g.Y = Y;
        g.ldA = ldA; g.ldR = ldR; g.ldY = ldY; g.K = K; g.transY = tY; g.rnd = rnd;
        return g;
    };

    const dim3 gi2c(4, 32, B_);
    const dim3 gdw(32, 4, B_);

    // im2col both branches
    im2col_kernel<3><<<gi2c, 256>>>(aop, ic3);
    im2col_kernel<5><<<gi2c, 256>>>(dop, ic5);

    // conv3 + conv5 merged (256 blocks)
    gemm_tc<<<dim3(8, 2, 16), 256, GEMM_SM>>>(
        mk(ic3, 2304, p_wq3, nullptr, 0, qb,  256, 2304, 0, 0),
        mk(ic5, 6400, p_wk5, nullptr, 0, kvb, 256, 6400, 0, 0));

    // ln1 both branches
    {
        LD a{qb, lnq1_w, lnq1_b, lnbq}, b{kvb, lnkv1_w, lnkv1_b, lnbkv};
        ln_kernel<<<2048, 256>>>(a, b);
    }

    // qkv (Q|K) both branches merged (512 blocks)
    gemm_tc<<<dim3(8, 4, 16), 256, GEMM_SM>>>(
        mk(lnbq,  256, p_saqkv, nullptr, 0, qkBq,  512, 256, 0, 1),
        mk(lnbkv, 256, p_skqkv, nullptr, 0, qkBkv, 512, 256, 0, 1));
    // vT both branches merged (256 blocks)
    gemm_tc<<<dim3(8, 2, 16), 256, GEMM_SM>>>(
        mk(lnbq,  256, p_saqkv + 512 * 256, nullptr, 0, vTq,  256, 256, 1, 1),
        mk(lnbkv, 256, p_skqkv + 512 * 256, nullptr, 0, vTkv, 256, 256, 1, 1));

    // attention both branches merged
    {
        AD a{qkBq, vTq, attq}, b{qkBkv, vTkv, attkv};
        attn_kernel<<<dim3(8, 4, 16), 256, ATTN_SM>>>(a, b);
    }

    // proj both branches merged (256 blocks)
    gemm_tc<<<dim3(8, 2, 16), 256, GEMM_SM>>>(
        mk(attq,  256, p_saprj, qb,  256, qb,  256, 256, 0, 0),
        mk(attkv, 256, p_skprj, kvb, 256, kvb, 256, 256, 0, 0));

    // ln2 both branches
    {
        LD a{qb, lnq2_w, lnq2_b, qn}, b{kvb, lnkv2_w, lnkv2_b, kvn};
        ln_kernel<<<2048, 256>>>(a, b);
    }

    // cross attention: ca_q + ca_k merged (256 blocks), ca_v single
    gemm_tc<<<dim3(8, 2, 16), 256, GEMM_SM>>>(
        mk(qn,  256, p_caq, nullptr, 0, qkBq,       512, 256, 0, 1),
        mk(kvn, 256, p_cak, nullptr, 0, qkBq + 256, 512, 256, 0, 1));
    {
        GD v = mk(kvn, 256, p_cav, nullptr, 0, vTq, 256, 256, 1, 1);
        gemm_tc<<<dim3(8, 2, 8), 256, GEMM_SM>>>(v, v);
    }
    {
        AD a{qkBq, vTq, attq};
        attn_kernel<<<dim3(8, 4, 8), 256, ATTN_SM>>>(a, a);
    }
    {
        GD p = mk(attq, 256, p_caprj, qb, 256, xbuf, 256, 256, 0, 0);
        gemm_tc<<<dim3(8, 2, 8), 256, GEMM_SM>>>(p, p);
    }

    // LeFF
    {
        LD a{xbuf, lnffn_w, lnffn_b, lnbq};
        ln_kernel<<<1024, 256>>>(a, a);
    }
    {
        GD l = mk(lnbq, 256, p_lin, nullptr, 0, h1, 1024, 256, 0, 0);
        gemm_tc<<<dim3(8, 8, 8), 256, GEMM_SM>>>(l, l);
    }
    dwgelu_kernel<<<gdw, 256>>>(h1, leff_dw, h2);
    {
        GD l = mk(h2, 1024, p_lout, xbuf, 256, out, 256, 1024, 1, 0);
        gemm_tc<<<dim3(8, 2, 8), 256, GEMM_SM>>>(l, l);
    }
}

// round 16
// speedup vs baseline: 1.1024x; 1.1024x over previous
#include <cuda_runtime.h>
#include <math.h>
#include <stdint.h>

#define B_    8
#define CCH   256
#define NPIX  1024
#define HID   1024
#define NTOK  (B_ * NPIX)   // 8192

__device__ float g_scratch[132ull * 1024 * 1024];

extern __shared__ char dyn_smem[];

__device__ __forceinline__ float to_tf32(float x) {
    float r;
    asm("cvt.rna.tf32.f32 %0, %1;" : "=f"(r) : "f"(x));
    return r;
}
__device__ __forceinline__ uint32_t smem_addr(const void* p) {
    return (uint32_t)__cvta_generic_to_shared(p);
}
__device__ __forceinline__ void cp16(uint32_t dst, const void* src) {
    asm volatile("cp.async.ca.shared.global [%0], [%1], 16;" :: "r"(dst), "l"(src));
}
// k-permutation within each 8-block: newpos(k) = (k&3)*2 + ((k>>2)&1)
__device__ __forceinline__ int permk(int k) {
    return (k & ~7) | (((k & 3) << 1) | ((k >> 2) & 1));
}

#define MMA_TF32(acc, a0, a1, a2, a3, b0, b1) \
    asm volatile( \
        "mma.sync.aligned.m16n8k8.row.col.f32.tf32.tf32.f32 " \
        "{%0,%1,%2,%3}, {%4,%5,%6,%7}, {%8,%9}, {%0,%1,%2,%3};" \
        : "+f"((acc)[0]), "+f"((acc)[1]), "+f"((acc)[2]), "+f"((acc)[3]) \
        : "r"(a0), "r"(a1), "r"(a2), "r"(a3), "r"(b0), "r"(b1))

// ---------------------------------------------------------------------------
// fused weight prep: tf32-round + k-permute + optional scale, one launch.
// Builds contiguous branch-pair weight copies for merged GEMM launches.
// ---------------------------------------------------------------------------
struct PrepArgs {
    const float* src[16];
    float*       dst[16];
    int          len[16];
    float        scl[16];
};
__global__ __launch_bounds__(256)
void prep_all(PrepArgs a)
{
    int i = blockIdx.x * 256 + threadIdx.x;
#pragma unroll
    for (int s = 0; s < 16; s++) {
        if (i < a.len[s]) {
            a.dst[s][permk(i)] = to_tf32(__ldg(a.src[s] + i) * a.scl[s]);
            return;
        }
        i -= a.len[s];
    }
}

// ---------------------------------------------------------------------------
// tf32 mma.sync GEMM, batch-16 capable. bz = blockIdx.z in [0,16):
//   A/R batch = bz (contiguous branch pair), W += (bz>>3)*Woff,
//   Y batch = bz & Ymask, Y += (bz>>3)*Yoff.
// PRE-PERMUTED tf32 inputs; fp32 Y (+R); rnd -> tf32 outputs; transY ->
// channel-major store. Block 128x128x32, cp.async double buffer.
// ---------------------------------------------------------------------------
__global__ __launch_bounds__(256, 2)
void gemm_tc(const float* __restrict__ A, int ldA,
             const float* __restrict__ W, int Woff,
             const float* __restrict__ R, int ldR,
             float* __restrict__ Y, int ldY, int Yoff, int Ymask,
             int K, int transY, int rnd)
{
    float* As = (float*)dyn_smem;        // [2][128*40]
    float* Bs = As + 2 * 5120;           // [2][128*40]

    const int bz = blockIdx.z;
    const int br = bz >> 3;
    const int yb = bz & Ymask;

    const int t = threadIdx.x;
    const int wid = t >> 5, lane = t & 31;
    const int g = lane >> 2, tig = lane & 3;
    const int warp_m = (wid & 1) * 64;
    const int warp_n = (wid >> 1) * 32;
    const int r0l = t >> 3, q0l = t & 7;

    const float* Ab = A + (size_t)bz * NPIX * ldA + (size_t)blockIdx.x * 128 * ldA;
    const float* Bb = W + (size_t)br * Woff + (size_t)blockIdx.y * 128 * (size_t)K;

    const uint32_t sA = smem_addr(As), sB = smem_addr(Bs);

    float acc[4][4][4];
#pragma unroll
    for (int im = 0; im < 4; im++)
#pragma unroll
        for (int in = 0; in < 4; in++)
#pragma unroll
            for (int c = 0; c < 4; c++) acc[im][in][c] = 0.f;

    const int nk = K >> 5;

#pragma unroll
    for (int i = 0; i < 4; i++) {
        const int r = r0l + i * 32;
        cp16(sA + (uint32_t)(r * 40 + q0l * 4) * 4, Ab + (size_t)r * ldA + q0l * 4);
        cp16(sB + (uint32_t)(r * 40 + q0l * 4) * 4, Bb + (size_t)r * K   + q0l * 4);
    }
    asm volatile("cp.async.commit_group;");

    for (int c = 0; c < nk; c++) {
        asm volatile("cp.async.wait_group 0;");
        __syncthreads();
        if (c + 1 < nk) {
            const int kk = (c + 1) << 5;
            const uint32_t boff = (uint32_t)((c + 1) & 1) * 5120;
#pragma unroll
            for (int i = 0; i < 4; i++) {
                const int r = r0l + i * 32;
                cp16(sA + (boff + r * 40 + q0l * 4) * 4, Ab + (size_t)r * ldA + kk + q0l * 4);
                cp16(sB + (boff + r * 40 + q0l * 4) * 4, Bb + (size_t)r * K   + kk + q0l * 4);
            }
            asm volatile("cp.async.commit_group;");
        }
        const float* Ac = As + (c & 1) * 5120;
        const float* Bc = Bs + (c & 1) * 5120;
#pragma unroll
        for (int ks = 0; ks < 4; ks++) {
            const int k0 = ks * 8;
            float2 au[4], al[4];
#pragma unroll
            for (int im = 0; im < 4; im++) {
                au[im] = *(const float2*)&Ac[(warp_m + im * 16 + g) * 40 + k0 + 2 * tig];
                al[im] = *(const float2*)&Ac[(warp_m + im * 16 + g + 8) * 40 + k0 + 2 * tig];
            }
#pragma unroll
            for (int in = 0; in < 4; in++) {
                const float2 bv = *(const float2*)&Bc[(warp_n + in * 8 + g) * 40 + k0 + 2 * tig];
#pragma unroll
                for (int im = 0; im < 4; im++) {
                    MMA_TF32(acc[im][in],
                             __float_as_uint(au[im].x), __float_as_uint(al[im].x),
                             __float_as_uint(au[im].y), __float_as_uint(al[im].y),
                             __float_as_uint(bv.x), __float_as_uint(bv.y));
                }
            }
        }
    }

    if (!transY) {
        float* Yb = Y + (size_t)br * Yoff + (size_t)yb * NPIX * ldY;
        const float* Rb = R ? R + (size_t)bz * NPIX * ldR : (const float*)0;
#pragma unroll
        for (int im = 0; im < 4; im++) {
#pragma unroll
            for (int half = 0; half < 2; half++) {
                const int tok = blockIdx.x * 128 + warp_m + im * 16 + g + half * 8;
#pragma unroll
                for (int in = 0; in < 4; in++) {
                    const int col = blockIdx.y * 128 + warp_n + in * 8 + tig * 2;
                    float2 v;
                    v.x = acc[im][in][half * 2 + 0];
                    v.y = acc[im][in][half * 2 + 1];
                    if (Rb) {
                        float2 rr = *(const float2*)(Rb + (size_t)tok * ldR + col);
                        v.x += rr.x; v.y += rr.y;
                    }
                    if (rnd) { v.x = to_tf32(v.x); v.y = to_tf32(v.y); }
                    *(float2*)(Yb + (size_t)tok * ldY + col) = v;
                }
            }
        }
    } else {
        float* Yb = Y + (size_t)br * Yoff + (size_t)yb * ldY * NPIX;
        const float* Rb = R ? R + (size_t)bz * NPIX * ldR : (const float*)0;
#pragma unroll
        for (int im = 0; im < 4; im++) {
#pragma unroll
            for (int half = 0; half < 2; half++) {
                const int tok = blockIdx.x * 128 + warp_m + im * 16 + g + half * 8;
#pragma unroll
                for (int in = 0; in < 4; in++) {
                    const int col = blockIdx.y * 128 + warp_n + in * 8 + tig * 2;
                    float v0 = acc[im][in][half * 2 + 0];
                    float v1 = acc[im][in][half * 2 + 1];
                    if (Rb) {
                        float2 rr = *(const float2*)(Rb + (size_t)tok * ldR + col);
                        v0 += rr.x; v1 += rr.y;
                    }
                    if (rnd) { v0 = to_tf32(v0); v1 = to_tf32(v1); }
                    Yb[(size_t)(col + 0) * NPIX + tok] = v0;
                    Yb[(size_t)(col + 1) * NPIX + tok] = v1;
                }
            }
        }
    }
}

// ---------------------------------------------------------------------------
// im2col: NCHW -> [B][1024 tok][C*KS*KS], tf32-rounded, k-permuted.
// ---------------------------------------------------------------------------
template <int KS>
__global__ __launch_bounds__(256)
void im2col_kernel(const float* __restrict__ in, float* __restrict__ out)
{
    constexpr int PAD  = KS / 2;
    constexpr int TAPS = KS * KS;
    constexpr int KTOT = CCH * TAPS;
    __shared__ float smv[64 * KS * 36];
    const int c0 = blockIdx.x * 64;
    const int h  = blockIdx.y;
    const int b  = blockIdx.z;
    const int t  = threadIdx.x;

    for (int e = t; e < 64 * KS * 36; e += 256) {
        const int cc = e % 36;
        const int r  = (e / 36) % KS;
        const int c  = e / (36 * KS);
        const int hh = h + r - PAD;
        const int ww = cc - PAD;
        float v = 0.f;
        if (hh >= 0 && hh < 32 && ww >= 0 && ww < 32)
            v = in[((size_t)b * CCH + c0 + c) * NPIX + hh * 32 + ww];
        smv[(c * KS + r) * 36 + cc] = v;
    }
    __syncthreads();
    for (int e = t; e < 32 * 64 * TAPS; e += 256) {
        const int w   = e / (64 * TAPS);
        const int rem = e % (64 * TAPS);
        const int c   = rem / TAPS;
        const int tap = rem % TAPS;
        const int ky  = tap / KS, kx = tap % KS;
        const int k   = (c0 + c) * TAPS + tap;
        out[((size_t)b * NPIX + h * 32 + w) * KTOT + permk(k)] =
            to_tf32(smv[(c * KS + ky) * 36 + (w + kx)]);
    }
}

// ---------------------------------------------------------------------------
// Dual LayerNorm over channels, token-major. Warp per token.
// blockIdx.x < nb0 -> set0 else set1 (x buffers contiguous; w/b selected).
// ---------------------------------------------------------------------------
struct LD { const float* x; const float* w; const float* b; float* y; };
__global__ __launch_bounds__(256)
void ln_kernel(LD d0, LD d1)
{
    const LD d = (blockIdx.x < 1024) ? d0 : d1;
    const int bx = blockIdx.x & 1023;
    const int warp = threadIdx.x >> 5, lane = threadIdx.x & 31;
    const size_t tok = (size_t)bx * 8 + warp;
    const float* xr = d.x + tok * CCH;
    float4 v0 = *(const float4*)(xr + lane * 4);
    float4 v1 = *(const float4*)(xr + 128 + lane * 4);
    float s  = v0.x + v0.y + v0.z + v0.w + v1.x + v1.y + v1.z + v1.w;
    float s2 = v0.x*v0.x + v0.y*v0.y + v0.z*v0.z + v0.w*v0.w
             + v1.x*v1.x + v1.y*v1.y + v1.z*v1.z + v1.w*v1.w;
#pragma unroll
    for (int o = 16; o > 0; o >>= 1) {
        s  += __shfl_xor_sync(0xffffffffu, s,  o);
        s2 += __shfl_xor_sync(0xffffffffu, s2, o);
    }
    const float mu = s * (1.f / 256.f);
    const float is = rsqrtf(s2 * (1.f / 256.f) - mu * mu + 1e-5f);
    float4 w0 = *(const float4*)(d.w + lane * 4);
    float4 w1 = *(const float4*)(d.w + 128 + lane * 4);
    float4 b0 = *(const float4*)(d.b + lane * 4);
    float4 b1 = *(const float4*)(d.b + 128 + lane * 4);
    float* yr = d.y + tok * CCH;
    float r0[4], r1[4];
    r0[0] = (v0.x - mu) * is * w0.x + b0.x; r0[1] = (v0.y - mu) * is * w0.y + b0.y;
    r0[2] = (v0.z - mu) * is * w0.z + b0.z; r0[3] = (v0.w - mu) * is * w0.w + b0.w;
    r1[0] = (v1.x - mu) * is * w1.x + b1.x; r1[1] = (v1.y - mu) * is * w1.y + b1.y;
    r1[2] = (v1.z - mu) * is * w1.z + b1.z; r1[3] = (v1.w - mu) * is * w1.w + b1.w;
#pragma unroll
    for (int j = 0; j < 4; j++) {
        yr[permk(lane * 4 + j)]       = to_tf32(r0[j]);
        yr[permk(128 + lane * 4 + j)] = to_tf32(r1[j]);
    }
}

// ---------------------------------------------------------------------------
// Flash attention, tf32 mma (single descriptor, R13 form). Inputs pre-rounded:
//   qk [B][1024][512] (Q pre-scaled 1/8), vT [B][256][1024].
// cp.async staging, 2 CTAs/SM. out [B][1024][256] tf32 k-permuted.
// ---------------------------------------------------------------------------
__global__ __launch_bounds__(256, 2)
void attn_kernel(const float* __restrict__ qk, const float* __restrict__ vT,
                 float* __restrict__ out)
{
    float* sm = (float*)dyn_smem;
    float* Qs = sm;                      // [128][68]
    float* Ks = Qs + 128 * 68;           // [64][68]
    float* Vt = Ks + 64 * 68;            // [64][68]
    float* Ps = Vt + 64 * 68;            // [128][68]

    const int b = blockIdx.z, h = blockIdx.y;
    const int q0 = blockIdx.x * 128;
    const int hq = h * 64;
    const float* qkb = qk + (size_t)b * NPIX * 512;
    const float* vtb = vT + ((size_t)b * 256 + hq) * NPIX;

    const int t = threadIdx.x;
    const int wid = t >> 5, lane = t & 31;
    const int g = lane >> 2, tig = lane & 3;
    const int w16 = wid * 16;

    const uint32_t sQ = smem_addr(Qs), sK = smem_addr(Ks), sV = smem_addr(Vt);

#pragma unroll
    for (int i = 0; i < 8; i++) {
        const int e = t + i * 256;
        const int r = e >> 4, c = e & 15;
        cp16(sQ + (uint32_t)(r * 68 + c * 4) * 4,
             qkb + (size_t)(q0 + r) * 512 + hq + c * 4);
    }
#pragma unroll
    for (int i = 0; i < 4; i++) {
        const int e = t + i * 256;
        const int rk = e >> 4, ck = e & 15;
        cp16(sK + (uint32_t)(rk * 68 + ck * 4) * 4, qkb + (size_t)rk * 512 + 256 + hq + ck * 4);
        cp16(sV + (uint32_t)(rk * 68 + ck * 4) * 4, vtb + (size_t)rk * NPIX + ck * 4);
    }
    asm volatile("cp.async.commit_group;");

    float oc[8][4];
#pragma unroll
    for (int n = 0; n < 8; n++)
#pragma unroll
        for (int c = 0; c < 4; c++) oc[n][c] = 0.f;
    float m0r = -1e30f, m1r = -1e30f, l0r = 0.f, l1r = 0.f;

    const int P0 = ((tig & 1) << 2) | (tig >> 1);

    for (int tile = 0; tile < 16; tile++) {
        asm volatile("cp.async.wait_group 0;");
        __syncthreads();

        float s[8][4];
#pragma unroll
        for (int n = 0; n < 8; n++)
#pragma unroll
            for (int c = 0; c < 4; c++) s[n][c] = 0.f;
#pragma unroll
        for (int ks = 0; ks < 8; ks++) {
            const int k0 = ks * 8;
            const uint32_t a0 = __float_as_uint(Qs[(w16 + g) * 68 + k0 + tig]);
            const uint32_t a1 = __float_as_uint(Qs[(w16 + g + 8) * 68 + k0 + tig]);
            const uint32_t a2 = __float_as_uint(Qs[(w16 + g) * 68 + k0 + tig + 4]);
            const uint32_t a3 = __float_as_uint(Qs[(w16 + g + 8) * 68 + k0 + tig + 4]);
#pragma unroll
            for (int n = 0; n < 8; n++) {
                const uint32_t b0 = __float_as_uint(Ks[(n * 8 + g) * 68 + k0 + tig]);
                const uint32_t b1 = __float_as_uint(Ks[(n * 8 + g) * 68 + k0 + tig + 4]);
                MMA_TF32(s[n], a0, a1, a2, a3, b0, b1);
            }
        }

        float t0 = -1e30f, t1 = -1e30f;
#pragma unroll
        for (int n = 0; n < 8; n++) {
            t0 = fmaxf(t0, fmaxf(s[n][0], s[n][1]));
            t1 = fmaxf(t1, fmaxf(s[n][2], s[n][3]));
        }
        t0 = fmaxf(t0, __shfl_xor_sync(0xffffffffu, t0, 1));
        t0 = fmaxf(t0, __shfl_xor_sync(0xffffffffu, t0, 2));
        t1 = fmaxf(t1, __shfl_xor_sync(0xffffffffu, t1, 1));
        t1 = fmaxf(t1, __shfl_xor_sync(0xffffffffu, t1, 2));
        const float nm0 = fmaxf(m0r, t0), nm1 = fmaxf(m1r, t1);
        const float cr0 = __expf(m0r - nm0), cr1 = __expf(m1r - nm1);
        m0r = nm0; m1r = nm1;
        float ls0 = 0.f, ls1 = 0.f;
#pragma unroll
        for (int n = 0; n < 8; n++) {
            const float p0 = __expf(s[n][0] - nm0);
            const float p1 = __expf(s[n][1] - nm0);
            const float p2 = __expf(s[n][2] - nm1);
            const float p3 = __expf(s[n][3] - nm1);
            ls0 += p0 + p1; ls1 += p2 + p3;
            float2 pa; pa.x = to_tf32(p0); pa.y = to_tf32(p1);
            float2 pb; pb.x = to_tf32(p2); pb.y = to_tf32(p3);
            *(float2*)&Ps[(w16 + g) * 68 + n * 8 + tig * 2] = pa;
            *(float2*)&Ps[(w16 + g + 8) * 68 + n * 8 + tig * 2] = pb;
        }
        ls0 += __shfl_xor_sync(0xffffffffu, ls0, 1);
        ls0 += __shfl_xor_sync(0xffffffffu, ls0, 2);
        ls1 += __shfl_xor_sync(0xffffffffu, ls1, 1);
        ls1 += __shfl_xor_sync(0xffffffffu, ls1, 2);
        l0r = l0r * cr0 + ls0;
        l1r = l1r * cr1 + ls1;
#pragma unroll
        for (int n = 0; n < 8; n++) {
            oc[n][0] *= cr0; oc[n][1] *= cr0;
            oc[n][2] *= cr1; oc[n][3] *= cr1;
        }
        __syncwarp();

#pragma unroll
        for (int ks = 0; ks < 8; ks++) {
            const int k0 = ks * 8;
            const uint32_t a0 = __float_as_uint(Ps[(w16 + g) * 68 + k0 + tig]);
            const uint32_t a1 = __float_as_uint(Ps[(w16 + g + 8) * 68 + k0 + tig]);
            const uint32_t a2 = __float_as_uint(Ps[(w16 + g) * 68 + k0 + tig + 4]);
            const uint32_t a3 = __float_as_uint(Ps[(w16 + g + 8) * 68 + k0 + tig + 4]);
#pragma unroll
            for (int n = 0; n < 8; n++) {
                const uint32_t b0 = __float_as_uint(Vt[(n * 8 + g) * 68 + k0 + tig]);
                const uint32_t b1 = __float_as_uint(Vt[(n * 8 + g) * 68 + k0 + tig + 4]);
                MMA_TF32(oc[n], a0, a1, a2, a3, b0, b1);
            }
        }

        if (tile < 15) {
            __syncthreads();
            const size_t m0 = (size_t)(tile + 1) * 64;
#pragma unroll
            for (int i = 0; i < 4; i++) {
                const int e = t + i * 256;
                const int rk = e >> 4, ck = e & 15;
                cp16(sK + (uint32_t)(rk * 68 + ck * 4) * 4,
                     qkb + (m0 + rk) * 512 + 256 + hq + ck * 4);
                cp16(sV + (uint32_t)(rk * 68 + ck * 4) * 4,
                     vtb + (size_t)rk * NPIX + m0 + ck * 4);
            }
            asm volatile("cp.async.commit_group;");
        }
    }

    const float i0 = 1.f / l0r, i1 = 1.f / l1r;
    float* ob = out + (size_t)b * NPIX * CCH;
#pragma unroll
    for (int n = 0; n < 8; n++) {
        float* r0p = ob + (size_t)(q0 + w16 + g) * CCH + hq + n * 8;
        float* r1p = ob + (size_t)(q0 + w16 + g + 8) * CCH + hq + n * 8;
        r0p[P0]     = to_tf32(oc[n][0] * i0);
        r0p[P0 + 2] = to_tf32(oc[n][1] * i0);
        r1p[P0]     = to_tf32(oc[n][2] * i1);
        r1p[P0 + 2] = to_tf32(oc[n][3] * i1);
    }
}

// ---------------------------------------------------------------------------
// Depthwise 3x3 + exact GELU, token-major [8192][1024].
// ---------------------------------------------------------------------------
__global__ __launch_bounds__(256)
void dwgelu_kernel(const float* __restrict__ x, const float* __restrict__ wd,
                   float* __restrict__ y)
{
    __shared__ float tile[10][34][32];
    const int c0 = blockIdx.x * 32;
    const int r0 = blockIdx.y * 8;
    const int b  = blockIdx.z;
    const int t  = threadIdx.x;
    const int ch = t & 31;

    for (int e = t; e < 10 * 34 * 32; e += 256) {
        const int cc  = e & 31;
        const int col = (e >> 5) % 34;
        const int r   = e / (34 * 32);
        const int hh = r0 + r - 1, ww = col - 1;
        float v = 0.f;
        if (hh >= 0 && hh < 32 && ww >= 0 && ww < 32)
            v = x[((size_t)b * NPIX + hh * 32 + ww) * HID + c0 + cc];
        tile[r][col][cc] = v;
    }
    float w9[9];
#pragma unroll
    for (int i = 0; i < 9; i++) w9[i] = wd[(size_t)(c0 + ch) * 9 + i];
    const int pc = permk(c0 + ch);
    __syncthreads();

    for (int e = t; e < 8 * 32 * 32; e += 256) {
        const int w = (e >> 5) & 31;
        const int r = e >> 10;
        float a = 0.f;
#pragma unroll
        for (int ky = 0; ky < 3; ky++)
#pragma unroll
            for (int kx = 0; kx < 3; kx++)
                a += w9[ky * 3 + kx] * tile[r + ky][w + kx][ch];
        y[((size_t)b * NPIX + (r0 + r) * 32 + w) * HID + pc] =
            to_tf32(0.5f * a * (1.f + erff(a * 0.70710678118654752f)));
    }
}

// ---------------------------------------------------------------------------
extern "C" void kernel_launch(void* const* d_in, const int* in_sizes, int n_in,
                              void* d_out, int out_size)
{
    const float* aop      = (const float*)d_in[0];
    const float* dop      = (const float*)d_in[1];
    const float* w_qconv  = (const float*)d_in[2];
    const float* w_kvconv = (const float*)d_in[3];
    const float* lnq1_w   = (const float*)d_in[4];
    const float* lnq1_b   = (const float*)d_in[5];
    const float* lnkv1_w  = (const float*)d_in[6];
    const float* lnkv1_b  = (const float*)d_in[7];
    const float* lnq2_w   = (const float*)d_in[8];
    const float* lnq2_b   = (const float*)d_in[9];
    const float* lnkv2_w  = (const float*)d_in[10];
    const float* lnkv2_b  = (const float*)d_in[11];
    const float* lnffn_w  = (const float*)d_in[12];
    const float* lnffn_b  = (const float*)d_in[13];
    const float* saq_qkv  = (const float*)d_in[14];
    const float* saq_proj = (const float*)d_in[15];
    const float* sakv_qkv = (const float*)d_in[16];
    const float* sakv_proj= (const float*)d_in[17];
    const float* ca_q     = (const float*)d_in[18];
    const float* ca_k     = (const float*)d_in[19];
    const float* ca_v     = (const float*)d_in[20];
    const float* ca_proj  = (const float*)d_in[21];
    const float* leff_in  = (const float*)d_in[22];
    const float* leff_dw  = (const float*)d_in[23];
    const float* leff_out = (const float*)d_in[24];
    float* out = (float*)d_out;

    float* S = nullptr;
    cudaGetSymbolAddress((void**)&S, g_scratch);
    const size_t C2 = (size_t)NTOK * CCH;       // 2M
    float* ic3   = S;
    float* ic5   = ic3   + (size_t)NTOK * 2304;
    float* qb    = ic5   + (size_t)NTOK * 6400;  // qb|kvb contiguous (batch-16)
    float* kvb   = qb    + C2;
    float* lnbq  = kvb   + C2;                   // lnbq|lnbkv contiguous
    float* lnbkv = lnbq  + C2;
    float* qn    = lnbkv + C2;                   // qn|kvn contiguous
    float* kvn   = qn    + C2;
    float* attq  = kvn   + C2;                   // attq|attkv contiguous
    float* attkv = attq  + C2;
    float* xbuf  = attkv + C2;
    float* qkBq  = xbuf  + C2;                   // qkBq|qkBkv contiguous
    float* qkBkv = qkBq  + (size_t)NTOK * 512;
    float* vTq   = qkBkv + (size_t)NTOK * 512;   // vTq|vTkv contiguous
    float* vTkv  = vTq   + C2;
    float* h1    = vTkv  + C2;
    float* h2    = h1    + (size_t)NTOK * HID;
    float* wp    = h2    + (size_t)NTOK * HID;

    // contiguous branch-pair weight copies
    float* p_wq3   = wp;
    float* p_wk5   = p_wq3   + 589824;
    float* p_qkw   = p_wk5   + 1638400;   // [2][512][256]
    float* p_vw    = p_qkw   + 262144;    // [2][256][256]
    float* p_prj   = p_vw    + 131072;    // [2][256][256]
    float* p_caqk  = p_prj   + 131072;    // [ca_q; ca_k]
    float* p_cav   = p_caqk  + 131072;
    float* p_caprj = p_cav   + 65536;
    float* p_lin   = p_caprj + 65536;
    float* p_lout  = p_lin   + 262144;

    const int GEMM_SM = 2 * 5120 * 2 * 4;    // 81920
    const int ATTN_SM = (128 * 68 + 64 * 68 + 64 * 68 + 128 * 68) * 4; // 104448
    cudaFuncSetAttribute(gemm_tc,     cudaFuncAttributeMaxDynamicSharedMemorySize, GEMM_SM);
    cudaFuncSetAttribute(attn_kernel, cudaFuncAttributeMaxDynamicSharedMemorySize, ATTN_SM);

    // fused weight prep. Q-projection rows pre-scaled by 0.125 (exact).
    PrepArgs pa;
    int s = 0;
    auto seg = [&](const float* src, float* dst, int len, float scl) {
        pa.src[s] = src; pa.dst[s] = dst; pa.len[s] = len; pa.scl[s] = scl; s++;
    };
    seg(w_qconv,           p_wq3,            589824,  1.f);
    seg(w_kvconv,          p_wk5,            1638400, 1.f);
    seg(saq_qkv,           p_qkw,            65536,   0.125f);  // sa-q Q
    seg(saq_qkv + 65536,   p_qkw + 65536,    65536,   1.f);     // sa-q K
    seg(sakv_qkv,          p_qkw + 131072,   65536,   0.125f);  // sa-kv Q
    seg(sakv_qkv + 65536,  p_qkw + 196608,   65536,   1.f);     // sa-kv K
    seg(saq_qkv + 131072,  p_vw,             65536,   1.f);     // sa-q V
    seg(sakv_qkv + 131072, p_vw + 65536,     65536,   1.f);     // sa-kv V
    seg(saq_proj,          p_prj,            65536,   1.f);
    seg(sakv_proj,         p_prj + 65536,    65536,   1.f);
    seg(ca_q,              p_caqk,           65536,   0.125f);
    seg(ca_k,              p_caqk + 65536,   65536,   1.f);
    seg(ca_v,              p_cav,            65536,   1.f);
    seg(ca_proj,           p_caprj,          65536,   1.f);
    seg(leff_in,           p_lin,            262144,  1.f);
    seg(leff_out,          p_lout,           262144,  1.f);
    int prep_total = 589824 + 1638400 + 8 * 65536 + 2 * 65536 + 4 * 65536 + 2 * 262144;
    prep_all<<<(prep_total + 255) / 256, 256>>>(pa);

    const dim3 gi2c(4, 32, B_);
    const dim3 gdw(32, 4, B_);

    // im2col both branches
    im2col_kernel<3><<<gi2c, 256>>>(aop, ic3);
    im2col_kernel<5><<<gi2c, 256>>>(dop, ic5);

    // convs SEPARATE (heterogeneous durations)
    gemm_tc<<<dim3(8, 2, 8), 256, GEMM_SM>>>(ic3, 2304, p_wq3, 0, nullptr, 0,
                                             qb, 256, 0, 15, 2304, 0, 0);
    gemm_tc<<<dim3(8, 2, 8), 256, GEMM_SM>>>(ic5, 6400, p_wk5, 0, nullptr, 0,
                                             kvb, 256, 0, 15, 6400, 0, 0);

    // ln1 both branches
    {
        LD a{qb, lnq1_w, lnq1_b, lnbq}, b{kvb, lnkv1_w, lnkv1_b, lnbkv};
        ln_kernel<<<2048, 256>>>(a, b);
    }

    // qkv (Q|K) merged batch-16 (512 blocks)
    gemm_tc<<<dim3(8, 4, 16), 256, GEMM_SM>>>(lnbq, 256, p_qkw, 131072, nullptr, 0,
                                              qkBq, 512, 0, 15, 256, 0, 1);
    // vT merged batch-16 (256 blocks)
    gemm_tc<<<dim3(8, 2, 16), 256, GEMM_SM>>>(lnbq, 256, p_vw, 65536, nullptr, 0,
                                              vTq, 256, 0, 15, 256, 1, 1);

    // attention per branch (256 blocks each, near-full)
    attn_kernel<<<dim3(8, 4, 8), 256, ATTN_SM>>>(qkBq,  vTq,  attq);
    attn_kernel<<<dim3(8, 4, 8), 256, ATTN_SM>>>(qkBkv, vTkv, attkv);

    // proj merged batch-16 (256 blocks), residual += qb|kvb
    gemm_tc<<<dim3(8, 2, 16), 256, GEMM_SM>>>(attq, 256, p_prj, 65536, qb, 256,
                                              qb, 256, 0, 15, 256, 0, 0);

    // ln2 both branches
    {
        LD a{qb, lnq2_w, lnq2_b, qn}, b{kvb, lnkv2_w, lnkv2_b, kvn};
        ln_kernel<<<2048, 256>>>(a, b);
    }

    // ca_q + ca_k merged: A = qn|kvn batch-16, Y = qkBq cols 0..255 / 256..511
    gemm_tc<<<dim3(8, 2, 16), 256, GEMM_SM>>>(qn, 256, p_caqk, 65536, nullptr, 0,
                                              qkBq, 512, 256, 7, 256, 0, 1);
    // ca_v single
    gemm_tc<<<dim3(8, 2, 8), 256, GEMM_SM>>>(kvn, 256, p_cav, 0, nullptr, 0,
                                             vTq, 256, 0, 15, 256, 1, 1);
    attn_kernel<<<dim3(8, 4, 8), 256, ATTN_SM>>>(qkBq, vTq, attq);
    gemm_tc<<<dim3(8, 2, 8), 256, GEMM_SM>>>(attq, 256, p_caprj, 0, qb, 256,
                                             xbuf, 256, 0, 15, 256, 0, 0);

    // LeFF
    {
        LD a{xbuf, lnffn_w, lnffn_b, lnbq};
        ln_kernel<<<1024, 256>>>(a, a);
    }
    gemm_tc<<<dim3(8, 8, 8), 256, GEMM_SM>>>(lnbq, 256, p_lin, 0, nullptr, 0,
                                             h1, 1024, 0, 15, 256, 0, 0);
    dwgelu_kernel<<<gdw, 256>>>(h1, leff_dw, h2);
    gemm_tc<<<dim3(8, 2, 8), 256, GEMM_SM>>>(h2, 1024, p_lout, 0, xbuf, 256,
                                             out, 256, 0, 15, 1024, 1, 0);
}